// round 3
// baseline (speedup 1.0000x reference)
#include <cuda_runtime.h>

// HakesPQ forward: out[n, m*16:(m+1)*16] = codebooks[m, k*, :]
// where k* = argmax_k -( (v2 - 2<v,c_k>) + |c_k|^2 )  evaluated with
// EXACT fp32 emulation of the reference (jax/XLA-CPU) arithmetic:
//   v2, vc, c2 = sequential fmaf chains over d ascending from 0,
//   score assembled as -( fl( fl(v2 - fl(2*vc)) + c2 ) ),
//   argmax ties -> lowest k (strict comparison ascending).
// N=32768, D=768, M=48 subquantizers, KSUB=16 codewords, DSUB=16 dims.

#define N_VECS   32768
#define D_DIM    768
#define M_SUB    48
#define KSUB     16
#define DSUB     16

#define NROWS    32          // rows (vectors) per block
#define NTHREADS 512         // 16 warps; warp w handles m = w, w+16, w+32
#define ROW_PAD  772         // 768+4: lane bank-start = 4*lane mod 32 -> conflict-free LDS.128

// shared layout (floats):
//   sv  [NROWS * ROW_PAD]           = 24704 floats (v tile, padded rows; reused for output)
//   scb [M_SUB * KSUB * DSUB]       = 12288 floats (codebook, natural [m][k][d])
//   sc2 [M_SUB * KSUB]              =   768 floats (|c|^2, ref-emulated)
#define SV_FLOATS   (NROWS * ROW_PAD)
#define SCB_FLOATS  (M_SUB * KSUB * DSUB)
#define SC2_FLOATS  (M_SUB * KSUB)
#define SMEM_BYTES  ((SV_FLOATS + SCB_FLOATS + SC2_FLOATS) * 4)

__global__ void __launch_bounds__(NTHREADS, 1)
pq_kernel(const float* __restrict__ vecs,
          const float* __restrict__ cb,
          float* __restrict__ out)
{
    extern __shared__ float smem[];
    float* sv  = smem;
    float* scb = smem + SV_FLOATS;
    float* sc2 = scb + SCB_FLOATS;

    const int tid = threadIdx.x;

    // ---- codebook into shared, natural layout (coalesced float4 copies) ----
    {
        const float4* src = (const float4*)cb;
        float4*       dst = (float4*)scb;
        #pragma unroll 2
        for (int i = tid; i < SCB_FLOATS / 4; i += NTHREADS) dst[i] = src[i];
    }
    // ---- |c|^2 with reference-emulated sequential fma chain ----
    for (int i = tid; i < SC2_FLOATS; i += NTHREADS) {
        const float* c = cb + i * DSUB;
        float s = 0.0f;
        #pragma unroll
        for (int d = 0; d < DSUB; d++) s = fmaf(c[d], c[d], s);
        sc2[i] = s;
    }

    // ---- stage 32-row v tile into shared (fully coalesced) ----
    const long long row0 = (long long)blockIdx.x * NROWS;
    const float4* vin = (const float4*)(vecs + row0 * D_DIM);
    #pragma unroll 4
    for (int i = tid; i < NROWS * (D_DIM / 4); i += NTHREADS) {
        int r  = i / (D_DIM / 4);
        int c4 = i % (D_DIM / 4);
        *(float4*)(sv + r * ROW_PAD + c4 * 4) = vin[i];
    }
    __syncthreads();

    const int warp = tid >> 5;
    const int lane = tid & 31;
    float* myrow = sv + lane * ROW_PAD;

    #pragma unroll 1
    for (int j = 0; j < 3; j++) {
        const int m = warp + j * 16;              // warp-uniform m
        float* myv = myrow + m * DSUB;            // 16B aligned (lane*3088 + m*64)

        // v chunk -> 16 registers (conflict-free LDS.128 via ROW_PAD)
        float4 a0 = *(const float4*)(myv + 0);
        float4 a1 = *(const float4*)(myv + 4);
        float4 a2 = *(const float4*)(myv + 8);
        float4 a3 = *(const float4*)(myv + 12);
        float v[16] = { a0.x, a0.y, a0.z, a0.w,
                        a1.x, a1.y, a1.z, a1.w,
                        a2.x, a2.y, a2.z, a2.w,
                        a3.x, a3.y, a3.z, a3.w };

        // v2: sequential fma chain ascending (reference emulation)
        float v2 = 0.0f;
        #pragma unroll
        for (int d = 0; d < DSUB; d++) v2 = fmaf(v[d], v[d], v2);

        const float* cm  = scb + m * (KSUB * DSUB);   // warp-uniform -> broadcast LDS
        const float* c2m = sc2 + m * KSUB;

        float best_t = 3.402823466e38f;   // minimize t = (v2 - 2vc) + c2  <=>  argmax p
        int   bk     = 0;
        #pragma unroll
        for (int k = 0; k < KSUB; ++k) {
            const float* ck = cm + k * DSUB;
            float acc = 0.0f;
            #pragma unroll
            for (int d = 0; d < DSUB; d++) acc = fmaf(v[d], ck[d], acc);
            // exact ref elementwise ops: (v2 - 2*vc) + c2 with RN at each step
            float t = __fadd_rn(__fsub_rn(v2, __fmul_rn(2.0f, acc)), c2m[k]);
            if (t < best_t) { best_t = t; bk = k; }   // strict: first max wins
        }

        // gather winning codeword, overwrite this task's (dead) v region
        const float4* gk = (const float4*)(cm + bk * DSUB);
        *(float4*)(myv + 0)  = gk[0];
        *(float4*)(myv + 4)  = gk[1];
        *(float4*)(myv + 8)  = gk[2];
        *(float4*)(myv + 12) = gk[3];
    }
    __syncthreads();

    // ---- write tile back, fully coalesced ----
    float4* vout = (float4*)(out + row0 * D_DIM);
    #pragma unroll 4
    for (int i = tid; i < NROWS * (D_DIM / 4); i += NTHREADS) {
        int r  = i / (D_DIM / 4);
        int c4 = i % (D_DIM / 4);
        vout[i] = *(float4*)(sv + r * ROW_PAD + c4 * 4);
    }
}

extern "C" void kernel_launch(void* const* d_in, const int* in_sizes, int n_in,
                              void* d_out, int out_size)
{
    const float* vecs = (const float*)d_in[0];   // (N, 768) f32
    const float* cb   = (const float*)d_in[1];   // (48, 16, 16) f32
    float*       out  = (float*)d_out;           // (N, 768) f32

    cudaFuncSetAttribute(pq_kernel, cudaFuncAttributeMaxDynamicSharedMemorySize, SMEM_BYTES);
    pq_kernel<<<N_VECS / NROWS, NTHREADS, SMEM_BYTES>>>(vecs, cb, out);
}